// round 15
// baseline (speedup 1.0000x reference)
#include <cuda_runtime.h>

// ---- problem constants ----
#define SB      1024
#define N1      8192
#define N2      16384
#define NTERMS  (N1 + N2)            // 24576
#define NC      12                   // chunks
#define CHUNK   2048                 // NC*CHUNK == NTERMS exactly; power of 2
#define CSHIFT  11
#define NSS     256
#define NT      512
#define ROWS    8
#define SPT     (SB / NT)            // 2 species per thread
#define NCTR    (NC * SB)            // 12288 sublists, chunk-major: sub = c*SB + s
#define NROLES  (2 * N1 + 3 * N2)    // 65536
#define LIST_CAP 77936               // 65536 + pads + alignment + slack
#define LCAP    8192                 // >= worst slice (3*CHUNK + SB + 8 = 7176)

// ---- persistent scratch (rebuilt every launch; structure is input-constant) ----
__device__ int g_cnt[2 * NCTR];      // (sublist, gain/loss) counts — static zero init
__device__ int g_curG[NCTR];
__device__ int g_curL[NCTR];
__device__ int g_off[NCTR + 1];      // padded sublist starts; chunk slices 8-aligned
__device__ int g_mid[NCTR];          // gain/loss boundary
__device__ __align__(16) unsigned short g_list[LIST_CAP];

// dynamic smem: tlo f4[CHUNK+1] | thi f4[CHUNK+1] | ylo f4[SB] | yhi f4[SB] | lbuf u16[LCAP]
// (reduction scratch red/tot aliases lbuf — lbuf dead by reduction time)
#define SMEM_BYTES ((2 * (CHUNK + 1) + 2 * SB) * 16 + LCAP * 2)   // 114,720 B

__inline__ __device__ float warp_red(float v) {
    #pragma unroll
    for (int o = 16; o > 0; o >>= 1) v += __shfl_xor_sync(0xFFFFFFFFu, v, o);
    return v;
}

// ---------- build kernels (3 launches) ----------
__device__ __forceinline__ void decode_role(
    int id, const int* p1, const int* r11, const int* p2,
    const int* r12, const int* r22, int& term, int& s, int& loss)
{
    if (id < N1)                 { term = id;                  s = __ldg(p1  + id);          loss = 0; }
    else if (id < 2 * N1)        { term = id - N1;             s = __ldg(r11 + id - N1);     loss = 1; }
    else if (id < 2 * N1 + N2)   { int j = id - 2 * N1;        term = N1 + j; s = __ldg(p2  + j); loss = 0; }
    else if (id < 2 * N1 + 2*N2) { int j = id - 2 * N1 - N2;   term = N1 + j; s = __ldg(r12 + j); loss = 1; }
    else                         { int j = id - 2 * N1 - 2*N2; term = N1 + j; s = __ldg(r22 + j); loss = 1; }
}

__global__ void k_count(const int* __restrict__ p1, const int* __restrict__ r11,
                        const int* __restrict__ p2, const int* __restrict__ r12,
                        const int* __restrict__ r22) {
    int id = blockIdx.x * blockDim.x + threadIdx.x;
    if (id >= NROLES) return;
    int term, s, loss;
    decode_role(id, p1, r11, p2, r12, r22, term, s, loss);
    int sub = ((term >> CSHIFT) << 10) + s;      // c*SB + s
    atomicAdd(&g_cnt[2 * sub + loss], 1);
}

__global__ void k_scan() {   // 1 CTA, 1024 threads; per-chunk shuffle scan
    __shared__ int wsum[32];
    __shared__ int chunkBase;
    const int t = threadIdx.x, lane = t & 31, w = t >> 5;
    if (t == 0) chunkBase = 0;
    __syncthreads();
    for (int c = 0; c < NC; c++) {
        const int sub = c * SB + t;
        const int gcv = g_cnt[2 * sub];
        const int lcv = g_cnt[2 * sub + 1];
        const int pcv = (gcv + lcv + 1) & ~1;          // pad sublist to 2
        int v = pcv;
        #pragma unroll
        for (int o = 1; o < 32; o <<= 1) {
            int x = __shfl_up_sync(0xFFFFFFFFu, v, o);
            if (lane >= o) v += x;
        }
        if (lane == 31) wsum[w] = v;
        __syncthreads();
        if (w == 0) {
            int wv = wsum[lane];
            #pragma unroll
            for (int o = 1; o < 32; o <<= 1) {
                int x = __shfl_up_sync(0xFFFFFFFFu, wv, o);
                if (lane >= o) wv += x;
            }
            wsum[lane] = wv;
        }
        __syncthreads();
        const int excl = chunkBase + (w ? wsum[w - 1] : 0) + v - pcv;
        g_off[sub]  = excl;
        g_curG[sub] = excl;
        g_mid[sub]  = excl + gcv;
        g_curL[sub] = excl + gcv;
        if ((gcv + lcv) < pcv)                          // odd count -> one dummy slot
            g_list[excl + gcv + lcv] = (unsigned short)CHUNK;
        g_cnt[2 * sub] = 0;                             // re-zero for next launch
        g_cnt[2 * sub + 1] = 0;
        __syncthreads();
        if (t == 1023) {
            int trueEnd = excl + pcv;                   // chunk's true slice end
            int aligned = (trueEnd + 7) & ~7;
            for (int p = trueEnd; p < aligned; p++)     // fill alignment gap
                g_list[p] = (unsigned short)CHUNK;
            chunkBase = aligned;
        }
        __syncthreads();
    }
    if (t == 0) g_off[NCTR] = chunkBase;
}

__global__ void k_fill(const int* __restrict__ p1, const int* __restrict__ r11,
                       const int* __restrict__ p2, const int* __restrict__ r12,
                       const int* __restrict__ r22) {
    int id = blockIdx.x * blockDim.x + threadIdx.x;
    if (id >= NROLES) return;
    int term, s, loss;
    decode_role(id, p1, r11, p2, r12, r22, term, s, loss);
    int sub = ((term >> CSHIFT) << 10) + s;
    int pos = loss ? atomicAdd(&g_curL[sub], 1) : atomicAdd(&g_curG[sub], 1);
    g_list[pos] = (unsigned short)(term & (CHUNK - 1));
}

// ---------- phase-2 pair processor (no surface logic in hot path) ----------
__device__ __forceinline__ void pair_acc(
    unsigned w, int pos, int m,
    const float4* __restrict__ tlo, const float4* __restrict__ thi,
    float (&net)[ROWS])
{
    const int e0 = (int)(w & 0xFFFFu), e1 = (int)(w >> 16);
    float4 l0 = tlo[e0], h0 = thi[e0];
    float4 l1 = tlo[e1], h1 = thi[e1];
    const float sg0 = (pos     < m) ? 1.f : -1.f;
    const float sg1 = (pos + 1 < m) ? 1.f : -1.f;
    net[0] = fmaf(sg0, l0.x, net[0]); net[1] = fmaf(sg0, l0.y, net[1]);
    net[2] = fmaf(sg0, l0.z, net[2]); net[3] = fmaf(sg0, l0.w, net[3]);
    net[4] = fmaf(sg0, h0.x, net[4]); net[5] = fmaf(sg0, h0.y, net[5]);
    net[6] = fmaf(sg0, h0.z, net[6]); net[7] = fmaf(sg0, h0.w, net[7]);
    net[0] = fmaf(sg1, l1.x, net[0]); net[1] = fmaf(sg1, l1.y, net[1]);
    net[2] = fmaf(sg1, l1.z, net[2]); net[3] = fmaf(sg1, l1.w, net[3]);
    net[4] = fmaf(sg1, h1.x, net[4]); net[5] = fmaf(sg1, h1.y, net[5]);
    net[6] = fmaf(sg1, h1.z, net[6]); net[7] = fmaf(sg1, h1.w, net[7]);
}

// ---------- main kernel: 8 rows/CTA, NT=512, 2 CTAs/SM, smem-staged list ----------
__global__ __launch_bounds__(NT, 2) void three_phase_rhs(
    const float* __restrict__ t_in, const float* __restrict__ y_in,
    const float* __restrict__ den_gas,
    const float* __restrict__ a1, const float* __restrict__ g1,
    const float* __restrict__ a2, const float* __restrict__ g2,
    const int* __restrict__ r11, const int* __restrict__ r12,
    const int* __restrict__ r22,
    const int* __restrict__ inds_s, const int* __restrict__ inds_m,
    float* __restrict__ out)
{
    extern __shared__ float4 smem4[];
    float4* tlo = smem4;                          // rows 0-3; [CHUNK] is zero dummy
    float4* thi = tlo + (CHUNK + 1);              // rows 4-7
    float4* ylo = thi + (CHUNK + 1);              // y rows 0-3
    float4* yhi = ylo + SB;                       // y rows 4-7
    unsigned short* lbuf = (unsigned short*)(yhi + SB);   // [LCAP]
    // reduction scratch aliases lbuf (live only after the chunk loop)
    float (*red)[NT / 32] = (float (*)[NT / 32])lbuf;
    float* tot = (float*)lbuf + 32 * (NT / 32);
    __shared__ float sh_pr[16];                   // nI[0..7] | c2[0..7]

    const int tid = threadIdx.x;
    const int b0 = blockIdx.x * ROWS;

    {
        const float* yr = y_in + (size_t)b0 * SB;
        for (int i = tid; i < SB; i += NT) {
            ylo[i] = make_float4(yr[i], yr[i + SB], yr[i + 2 * SB], yr[i + 3 * SB]);
            yhi[i] = make_float4(yr[i + 4 * SB], yr[i + 5 * SB], yr[i + 6 * SB], yr[i + 7 * SB]);
        }
    }
    if (tid == 0) {
        tlo[CHUNK] = make_float4(0.f, 0.f, 0.f, 0.f);
        thi[CHUNK] = make_float4(0.f, 0.f, 0.f, 0.f);
    }
    if (tid < ROWS) {                             // per-row params -> shared
        float T = 10.0f + 5.0f / (1.0f + __expf(-__ldg(t_in + b0 + tid)));
        sh_pr[tid] = -1.0f / T;
        sh_pr[tid + 8] = sqrtf(T * (1.0f / 300.0f)) * __ldg(den_gas + b0 + tid);
    }
    const int s0 = __ldg(&inds_s[0]), m0 = __ldg(&inds_m[0]);

    bool isSurf[SPT], isMant[SPT];
    #pragma unroll
    for (int gsp = 0; gsp < SPT; gsp++) {
        int s = tid + gsp * NT;
        isSurf[gsp] = (unsigned)(s - s0) < NSS;
        isMant[gsp] = (unsigned)(s - m0) < NSS;
    }
    __syncthreads();

    float net[SPT][ROWS];
    float ng[ROWS];
    #pragma unroll
    for (int g = 0; g < SPT; g++)
        #pragma unroll
        for (int r = 0; r < ROWS; r++) net[g][r] = 0.f;
    #pragma unroll
    for (int r = 0; r < ROWS; r++) ng[r] = 0.f;

    for (int c = 0; c < NC; c++) {
        const int base = c * CHUNK;

        // prefetch this chunk's sublist offsets (L2 latency hides under phase 1)
        int beg[SPT], mid[SPT], end[SPT];
        #pragma unroll
        for (int gsp = 0; gsp < SPT; gsp++) {
            const int ob = c * SB + tid + gsp * NT;
            beg[gsp] = __ldg(&g_off[ob]);
            mid[gsp] = __ldg(&g_mid[ob]);
            end[gsp] = __ldg(&g_off[ob + 1]);
        }
        const int sliceBeg = __ldg(&g_off[c * SB]);           // 8-aligned
        const int sliceEnd = __ldg(&g_off[(c + 1) * SB]);     // 8-aligned

        // stage this chunk's list slice into shared (slice <= 7176 < LCAP always)
        {
            const int n16 = (sliceEnd - sliceBeg) >> 3;
            const uint4* src = (const uint4*)(g_list + sliceBeg);
            uint4* dst = (uint4*)lbuf;
            for (int k = tid; k < n16; k += NT) dst[k] = src[k];
        }
        const unsigned short* lpt = lbuf - sliceBeg;  // index with global position

        // ---- phase 1: terms for this chunk ----
        {
            float nI[ROWS], c2[ROWS];
            #pragma unroll
            for (int r = 0; r < ROWS; r++) { nI[r] = sh_pr[r]; c2[r] = sh_pr[r + 8]; }
            for (int jj = tid; jj < CHUNK; jj += NT) {
                int j = base + jj;
                float4 lo, hi;
                if (j < N1) {
                    float a = __ldg(a1 + j), g = __ldg(g1 + j);
                    int   rr = __ldg(r11 + j);
                    float4 ya = ylo[rr], yb = yhi[rr];
                    lo.x = a * __expf(g * nI[0]) * ya.x;
                    lo.y = a * __expf(g * nI[1]) * ya.y;
                    lo.z = a * __expf(g * nI[2]) * ya.z;
                    lo.w = a * __expf(g * nI[3]) * ya.w;
                    hi.x = a * __expf(g * nI[4]) * yb.x;
                    hi.y = a * __expf(g * nI[5]) * yb.y;
                    hi.z = a * __expf(g * nI[6]) * yb.z;
                    hi.w = a * __expf(g * nI[7]) * yb.w;
                } else {
                    int j2 = j - N1;
                    float a = __ldg(a2 + j2), g = __ldg(g2 + j2);
                    int  rA = __ldg(r12 + j2), rB = __ldg(r22 + j2);
                    float4 yaA = ylo[rA], yaB = ylo[rB];
                    float4 ybA = yhi[rA], ybB = yhi[rB];
                    lo.x = a * c2[0] * __expf(g * nI[0]) * yaA.x * yaB.x;
                    lo.y = a * c2[1] * __expf(g * nI[1]) * yaA.y * yaB.y;
                    lo.z = a * c2[2] * __expf(g * nI[2]) * yaA.z * yaB.z;
                    lo.w = a * c2[3] * __expf(g * nI[3]) * yaA.w * yaB.w;
                    hi.x = a * c2[4] * __expf(g * nI[4]) * ybA.x * ybB.x;
                    hi.y = a * c2[5] * __expf(g * nI[5]) * ybA.y * ybB.y;
                    hi.z = a * c2[6] * __expf(g * nI[6]) * ybA.z * ybB.z;
                    hi.w = a * c2[7] * __expf(g * nI[7]) * ybA.w * ybB.w;
                }
                tlo[jj] = lo;
                thi[jj] = hi;
            }
        }
        __syncthreads();   // terms + lbuf both ready

        // ---- phase 2: gather from smem-staged list (quad-step + pair tail) ----
        #pragma unroll
        for (int gsp = 0; gsp < SPT; gsp++) {
            const int m = mid[gsp], e = end[gsp];
            int i = beg[gsp];
            for (; i + 4 <= e; i += 4) {
                const unsigned wA = *(const unsigned*)(lpt + i);
                const unsigned wB = *(const unsigned*)(lpt + i + 2);
                pair_acc(wA, i,     m, tlo, thi, net[gsp]);
                pair_acc(wB, i + 2, m, tlo, thi, net[gsp]);
            }
            if (i < e) {
                const unsigned wA = *(const unsigned*)(lpt + i);
                pair_acc(wA, i, m, tlo, thi, net[gsp]);
            }
            // surface loss pass: loss segment only (pad dummies read zero)
            if (isSurf[gsp]) {
                for (int k = m; k < e; k++) {
                    const int ev = (int)lpt[k];
                    float4 l = tlo[ev], h = thi[ev];
                    ng[0] += l.x; ng[1] += l.y; ng[2] += l.z; ng[3] += l.w;
                    ng[4] += h.x; ng[5] += h.y; ng[6] += h.z; ng[7] += h.w;
                }
            }
        }
        __syncthreads();
    }

    // ---- reductions: per row {gain, loss, ysurf, ymant} (red/tot alias lbuf) ----
    float vals[32];
    #pragma unroll
    for (int v = 0; v < 32; v++) vals[v] = 0.f;
    #pragma unroll
    for (int gsp = 0; gsp < SPT; gsp++) {
        int s = tid + gsp * NT;
        float4 ya = ylo[s], yb = yhi[s];
        float yr[ROWS] = { ya.x, ya.y, ya.z, ya.w, yb.x, yb.y, yb.z, yb.w };
        if (isSurf[gsp]) {
            #pragma unroll
            for (int r = 0; r < ROWS; r++) {
                vals[4 * r + 0] += net[gsp][r] + ng[r];
                vals[4 * r + 1] += ng[r];
                vals[4 * r + 2] += yr[r];
            }
        } else if (isMant[gsp]) {
            #pragma unroll
            for (int r = 0; r < ROWS; r++) vals[4 * r + 3] += yr[r];
        }
    }
    {
        int lane = tid & 31, w = tid >> 5;
        #pragma unroll
        for (int v = 0; v < 32; v++) {
            float x = warp_red(vals[v]);
            if (lane == 0) red[v][w] = x;
        }
        __syncthreads();
        if (tid < 32) {
            float s = 0.f;
            #pragma unroll
            for (int i = 0; i < NT / 32; i++) s += red[tid][i];
            tot[tid] = s;
        }
        __syncthreads();
    }

    float ks2m[ROWS], km2s[ROWS];
    #pragma unroll
    for (int r = 0; r < ROWS; r++) {
        ks2m[r] = tot[4 * r + 0] / (tot[4 * r + 2] + 1e-10f);
        km2s[r] = tot[4 * r + 1] / (tot[4 * r + 3] + 1e-10f);
    }

    // ---- epilogue: surface<->mantle transfer + write out ----
    #pragma unroll
    for (int gsp = 0; gsp < SPT; gsp++) {
        int s = tid + gsp * NT;
        float dy[ROWS];
        #pragma unroll
        for (int r = 0; r < ROWS; r++) dy[r] = net[gsp][r];
        unsigned ds = (unsigned)(s - s0), dm = (unsigned)(s - m0);
        if (ds < NSS) {
            float4 ma = ylo[m0 + ds], mb = yhi[m0 + ds];
            float4 sa = ylo[s],       sb = yhi[s];
            float ymr[ROWS] = { ma.x, ma.y, ma.z, ma.w, mb.x, mb.y, mb.z, mb.w };
            float ysr[ROWS] = { sa.x, sa.y, sa.z, sa.w, sb.x, sb.y, sb.z, sb.w };
            #pragma unroll
            for (int r = 0; r < ROWS; r++) dy[r] += km2s[r] * ymr[r] - ks2m[r] * ysr[r];
        } else if (dm < NSS) {
            float4 sa = ylo[s0 + dm], sb = yhi[s0 + dm];
            float4 ma = ylo[s],       mb = yhi[s];
            float ysr[ROWS] = { sa.x, sa.y, sa.z, sa.w, sb.x, sb.y, sb.z, sb.w };
            float ymr[ROWS] = { ma.x, ma.y, ma.z, ma.w, mb.x, mb.y, mb.z, mb.w };
            #pragma unroll
            for (int r = 0; r < ROWS; r++) dy[r] += ks2m[r] * ysr[r] - km2s[r] * ymr[r];
        }
        #pragma unroll
        for (int r = 0; r < ROWS; r++)
            out[(size_t)(b0 + r) * SB + s] = dy[r];
    }
}

extern "C" void kernel_launch(void* const* d_in, const int* in_sizes, int n_in,
                              void* d_out, int out_size) {
    const float* t_in    = (const float*)d_in[0];
    const float* y_in    = (const float*)d_in[1];
    const float* den_gas = (const float*)d_in[2];
    const float* a1      = (const float*)d_in[3];
    const float* g1      = (const float*)d_in[4];
    const float* a2      = (const float*)d_in[5];
    const float* g2      = (const float*)d_in[6];
    const int*   r11     = (const int*)d_in[7];
    const int*   p1      = (const int*)d_in[8];
    const int*   r12     = (const int*)d_in[9];
    const int*   r22     = (const int*)d_in[10];
    const int*   p2      = (const int*)d_in[11];
    const int*   inds_s  = (const int*)d_in[12];
    const int*   inds_m  = (const int*)d_in[13];
    float*       out     = (float*)d_out;

    const int B = in_sizes[0];

    cudaFuncSetAttribute(three_phase_rhs,
                         cudaFuncAttributeMaxDynamicSharedMemorySize, SMEM_BYTES);

    k_count<<<(NROLES + 255) / 256, 256>>>(p1, r11, p2, r12, r22);
    k_scan <<<1, 1024>>>();
    k_fill <<<(NROLES + 255) / 256, 256>>>(p1, r11, p2, r12, r22);

    three_phase_rhs<<<B / ROWS, NT, SMEM_BYTES>>>(
        t_in, y_in, den_gas, a1, g1, a2, g2,
        r11, r12, r22, inds_s, inds_m, out);
}

// round 16
// speedup vs baseline: 1.1915x; 1.1915x over previous
#include <cuda_runtime.h>

// ---- problem constants ----
#define SB      1024
#define N1      8192
#define N2      16384
#define NTERMS  (N1 + N2)            // 24576
#define NC      12                   // chunks
#define CHUNK   2048                 // NC*CHUNK == NTERMS exactly; power of 2
#define CSHIFT  11
#define NSS     256
#define NT      512
#define ROWS    8
#define SPT     (SB / NT)            // 2 species per thread
#define NCTR    (NC * SB)            // 12288 sublists, chunk-major: sub = c*SB + s
#define NROLES  (2 * N1 + 3 * N2)    // 65536
#define LIST_CAP 77936               // 65536 + pads + alignment + slack
#define LCAP    8192                 // >= worst slice (3*CHUNK + SB + 8 = 7176)

// ---- persistent scratch (rebuilt every launch; structure is input-constant) ----
__device__ int g_cnt[2 * NCTR];      // (sublist, gain/loss) counts — static zero init
__device__ int g_curG[NCTR];
__device__ int g_curL[NCTR];
__device__ int g_off[NCTR + 1];      // padded sublist starts; chunk slices 8-aligned
__device__ int g_mid[NCTR];          // gain/loss boundary
__device__ __align__(16) unsigned short g_list[LIST_CAP];

// dynamic smem: tlo f4[CHUNK+1] | thi f4[CHUNK+1] | ylo f4[SB] | yhi f4[SB] | lbuf u16[LCAP]
// (reduction scratch red/tot aliases lbuf — lbuf dead by reduction time)
#define SMEM_BYTES ((2 * (CHUNK + 1) + 2 * SB) * 16 + LCAP * 2)   // 114,720 B

__inline__ __device__ float warp_red(float v) {
    #pragma unroll
    for (int o = 16; o > 0; o >>= 1) v += __shfl_xor_sync(0xFFFFFFFFu, v, o);
    return v;
}

// ---------- build kernels (3 launches) ----------
__device__ __forceinline__ void decode_role(
    int id, const int* p1, const int* r11, const int* p2,
    const int* r12, const int* r22, int& term, int& s, int& loss)
{
    if (id < N1)                 { term = id;                  s = __ldg(p1  + id);          loss = 0; }
    else if (id < 2 * N1)        { term = id - N1;             s = __ldg(r11 + id - N1);     loss = 1; }
    else if (id < 2 * N1 + N2)   { int j = id - 2 * N1;        term = N1 + j; s = __ldg(p2  + j); loss = 0; }
    else if (id < 2 * N1 + 2*N2) { int j = id - 2 * N1 - N2;   term = N1 + j; s = __ldg(r12 + j); loss = 1; }
    else                         { int j = id - 2 * N1 - 2*N2; term = N1 + j; s = __ldg(r22 + j); loss = 1; }
}

__global__ void k_count(const int* __restrict__ p1, const int* __restrict__ r11,
                        const int* __restrict__ p2, const int* __restrict__ r12,
                        const int* __restrict__ r22) {
    int id = blockIdx.x * blockDim.x + threadIdx.x;
    if (id >= NROLES) return;
    int term, s, loss;
    decode_role(id, p1, r11, p2, r12, r22, term, s, loss);
    int sub = ((term >> CSHIFT) << 10) + s;      // c*SB + s
    atomicAdd(&g_cnt[2 * sub + loss], 1);
}

__global__ void k_scan() {   // 1 CTA, 1024 threads; per-chunk shuffle scan
    __shared__ int wsum[32];
    __shared__ int chunkBase;
    const int t = threadIdx.x, lane = t & 31, w = t >> 5;
    if (t == 0) chunkBase = 0;
    __syncthreads();
    for (int c = 0; c < NC; c++) {
        const int sub = c * SB + t;
        const int gcv = g_cnt[2 * sub];
        const int lcv = g_cnt[2 * sub + 1];
        const int pcv = (gcv + lcv + 1) & ~1;          // pad sublist to 2
        int v = pcv;
        #pragma unroll
        for (int o = 1; o < 32; o <<= 1) {
            int x = __shfl_up_sync(0xFFFFFFFFu, v, o);
            if (lane >= o) v += x;
        }
        if (lane == 31) wsum[w] = v;
        __syncthreads();
        if (w == 0) {
            int wv = wsum[lane];
            #pragma unroll
            for (int o = 1; o < 32; o <<= 1) {
                int x = __shfl_up_sync(0xFFFFFFFFu, wv, o);
                if (lane >= o) wv += x;
            }
            wsum[lane] = wv;
        }
        __syncthreads();
        const int excl = chunkBase + (w ? wsum[w - 1] : 0) + v - pcv;
        g_off[sub]  = excl;
        g_curG[sub] = excl;
        g_mid[sub]  = excl + gcv;
        g_curL[sub] = excl + gcv;
        if ((gcv + lcv) < pcv)                          // odd count -> one dummy slot
            g_list[excl + gcv + lcv] = (unsigned short)CHUNK;
        g_cnt[2 * sub] = 0;                             // re-zero for next launch
        g_cnt[2 * sub + 1] = 0;
        __syncthreads();
        if (t == 1023) {
            int trueEnd = excl + pcv;                   // chunk's true slice end
            int aligned = (trueEnd + 7) & ~7;
            for (int p = trueEnd; p < aligned; p++)     // fill alignment gap
                g_list[p] = (unsigned short)CHUNK;
            chunkBase = aligned;
        }
        __syncthreads();
    }
    if (t == 0) g_off[NCTR] = chunkBase;
}

__global__ void k_fill(const int* __restrict__ p1, const int* __restrict__ r11,
                       const int* __restrict__ p2, const int* __restrict__ r12,
                       const int* __restrict__ r22) {
    int id = blockIdx.x * blockDim.x + threadIdx.x;
    if (id >= NROLES) return;
    int term, s, loss;
    decode_role(id, p1, r11, p2, r12, r22, term, s, loss);
    int sub = ((term >> CSHIFT) << 10) + s;
    int pos = loss ? atomicAdd(&g_curL[sub], 1) : atomicAdd(&g_curG[sub], 1);
    g_list[pos] = (unsigned short)(term & (CHUNK - 1));
}

// ---------- main kernel: 8 rows/CTA, NT=512, 2 CTAs/SM, smem-staged list ----------
__global__ __launch_bounds__(NT, 2) void three_phase_rhs(
    const float* __restrict__ t_in, const float* __restrict__ y_in,
    const float* __restrict__ den_gas,
    const float* __restrict__ a1, const float* __restrict__ g1,
    const float* __restrict__ a2, const float* __restrict__ g2,
    const int* __restrict__ r11, const int* __restrict__ r12,
    const int* __restrict__ r22,
    const int* __restrict__ inds_s, const int* __restrict__ inds_m,
    float* __restrict__ out)
{
    extern __shared__ float4 smem4[];
    float4* tlo = smem4;                          // rows 0-3; [CHUNK] is zero dummy
    float4* thi = tlo + (CHUNK + 1);              // rows 4-7
    float4* ylo = thi + (CHUNK + 1);              // y rows 0-3
    float4* yhi = ylo + SB;                       // y rows 4-7
    unsigned short* lbuf = (unsigned short*)(yhi + SB);   // [LCAP]
    // reduction scratch aliases lbuf (live only after the chunk loop)
    float (*red)[NT / 32] = (float (*)[NT / 32])lbuf;
    float* tot = (float*)lbuf + 32 * (NT / 32);
    __shared__ float sh_pr[16];                   // nI[0..7] | c2[0..7]

    const int tid = threadIdx.x;
    const int b0 = blockIdx.x * ROWS;

    {
        const float* yr = y_in + (size_t)b0 * SB;
        for (int i = tid; i < SB; i += NT) {
            ylo[i] = make_float4(yr[i], yr[i + SB], yr[i + 2 * SB], yr[i + 3 * SB]);
            yhi[i] = make_float4(yr[i + 4 * SB], yr[i + 5 * SB], yr[i + 6 * SB], yr[i + 7 * SB]);
        }
    }
    if (tid == 0) {
        tlo[CHUNK] = make_float4(0.f, 0.f, 0.f, 0.f);
        thi[CHUNK] = make_float4(0.f, 0.f, 0.f, 0.f);
    }
    if (tid < ROWS) {                             // per-row params -> shared
        float T = 10.0f + 5.0f / (1.0f + __expf(-__ldg(t_in + b0 + tid)));
        sh_pr[tid] = -1.0f / T;
        sh_pr[tid + 8] = sqrtf(T * (1.0f / 300.0f)) * __ldg(den_gas + b0 + tid);
    }
    const int s0 = __ldg(&inds_s[0]), m0 = __ldg(&inds_m[0]);

    bool isSurf[SPT], isMant[SPT];
    #pragma unroll
    for (int gsp = 0; gsp < SPT; gsp++) {
        int s = tid + gsp * NT;
        isSurf[gsp] = (unsigned)(s - s0) < NSS;
        isMant[gsp] = (unsigned)(s - m0) < NSS;
    }
    __syncthreads();

    float net[SPT][ROWS];
    float ng[ROWS];
    #pragma unroll
    for (int g = 0; g < SPT; g++)
        #pragma unroll
        for (int r = 0; r < ROWS; r++) net[g][r] = 0.f;
    #pragma unroll
    for (int r = 0; r < ROWS; r++) ng[r] = 0.f;

    for (int c = 0; c < NC; c++) {
        const int base = c * CHUNK;

        // prefetch this chunk's sublist offsets (L2 latency hides under phase 1)
        int beg[SPT], mid[SPT], end[SPT];
        #pragma unroll
        for (int gsp = 0; gsp < SPT; gsp++) {
            const int ob = c * SB + tid + gsp * NT;
            beg[gsp] = __ldg(&g_off[ob]);
            mid[gsp] = __ldg(&g_mid[ob]);
            end[gsp] = __ldg(&g_off[ob + 1]);
        }
        const int sliceBeg = __ldg(&g_off[c * SB]);           // 8-aligned
        const int sliceEnd = __ldg(&g_off[(c + 1) * SB]);     // 8-aligned

        // stage this chunk's list slice into shared (slice <= 7176 < LCAP always)
        {
            const int n16 = (sliceEnd - sliceBeg) >> 3;
            const uint4* src = (const uint4*)(g_list + sliceBeg);
            uint4* dst = (uint4*)lbuf;
            for (int k = tid; k < n16; k += NT) dst[k] = src[k];
        }
        const unsigned short* lpt = lbuf - sliceBeg;  // index with global position

        // ---- phase 1: terms for this chunk ----
        {
            float nI[ROWS], c2[ROWS];
            #pragma unroll
            for (int r = 0; r < ROWS; r++) { nI[r] = sh_pr[r]; c2[r] = sh_pr[r + 8]; }
            for (int jj = tid; jj < CHUNK; jj += NT) {
                int j = base + jj;
                float4 lo, hi;
                if (j < N1) {
                    float a = __ldg(a1 + j), g = __ldg(g1 + j);
                    int   rr = __ldg(r11 + j);
                    float4 ya = ylo[rr], yb = yhi[rr];
                    lo.x = a * __expf(g * nI[0]) * ya.x;
                    lo.y = a * __expf(g * nI[1]) * ya.y;
                    lo.z = a * __expf(g * nI[2]) * ya.z;
                    lo.w = a * __expf(g * nI[3]) * ya.w;
                    hi.x = a * __expf(g * nI[4]) * yb.x;
                    hi.y = a * __expf(g * nI[5]) * yb.y;
                    hi.z = a * __expf(g * nI[6]) * yb.z;
                    hi.w = a * __expf(g * nI[7]) * yb.w;
                } else {
                    int j2 = j - N1;
                    float a = __ldg(a2 + j2), g = __ldg(g2 + j2);
                    int  rA = __ldg(r12 + j2), rB = __ldg(r22 + j2);
                    float4 yaA = ylo[rA], yaB = ylo[rB];
                    float4 ybA = yhi[rA], ybB = yhi[rB];
                    lo.x = a * c2[0] * __expf(g * nI[0]) * yaA.x * yaB.x;
                    lo.y = a * c2[1] * __expf(g * nI[1]) * yaA.y * yaB.y;
                    lo.z = a * c2[2] * __expf(g * nI[2]) * yaA.z * yaB.z;
                    lo.w = a * c2[3] * __expf(g * nI[3]) * yaA.w * yaB.w;
                    hi.x = a * c2[4] * __expf(g * nI[4]) * ybA.x * ybB.x;
                    hi.y = a * c2[5] * __expf(g * nI[5]) * ybA.y * ybB.y;
                    hi.z = a * c2[6] * __expf(g * nI[6]) * ybA.z * ybB.z;
                    hi.w = a * c2[7] * __expf(g * nI[7]) * ybA.w * ybB.w;
                }
                tlo[jj] = lo;
                thi[jj] = hi;
            }
        }
        __syncthreads();   // terms + lbuf both ready

        // ---- phase 2: gather from smem-staged list (R14 shape; no bounds branch) ----
        #pragma unroll
        for (int gsp = 0; gsp < SPT; gsp++) {
            const bool surf = isSurf[gsp];
            const int m = mid[gsp], e = end[gsp];
            for (int i = beg[gsp]; i < e; i += 2) {
                const unsigned w = *(const unsigned*)(lpt + i);
                const int e0 = (int)(w & 0xFFFFu), e1 = (int)(w >> 16);
                float4 l0 = tlo[e0], h0 = thi[e0];
                float4 l1 = tlo[e1], h1 = thi[e1];
                const float sg0 = (i     < m) ? 1.f : -1.f;
                const float sg1 = (i + 1 < m) ? 1.f : -1.f;
                net[gsp][0] = fmaf(sg0, l0.x, net[gsp][0]);
                net[gsp][1] = fmaf(sg0, l0.y, net[gsp][1]);
                net[gsp][2] = fmaf(sg0, l0.z, net[gsp][2]);
                net[gsp][3] = fmaf(sg0, l0.w, net[gsp][3]);
                net[gsp][4] = fmaf(sg0, h0.x, net[gsp][4]);
                net[gsp][5] = fmaf(sg0, h0.y, net[gsp][5]);
                net[gsp][6] = fmaf(sg0, h0.z, net[gsp][6]);
                net[gsp][7] = fmaf(sg0, h0.w, net[gsp][7]);
                net[gsp][0] = fmaf(sg1, l1.x, net[gsp][0]);
                net[gsp][1] = fmaf(sg1, l1.y, net[gsp][1]);
                net[gsp][2] = fmaf(sg1, l1.z, net[gsp][2]);
                net[gsp][3] = fmaf(sg1, l1.w, net[gsp][3]);
                net[gsp][4] = fmaf(sg1, h1.x, net[gsp][4]);
                net[gsp][5] = fmaf(sg1, h1.y, net[gsp][5]);
                net[gsp][6] = fmaf(sg1, h1.z, net[gsp][6]);
                net[gsp][7] = fmaf(sg1, h1.w, net[gsp][7]);
                if (surf) {                       // warp-uniform
                    if (i >= m) {
                        ng[0] += l0.x; ng[1] += l0.y; ng[2] += l0.z; ng[3] += l0.w;
                        ng[4] += h0.x; ng[5] += h0.y; ng[6] += h0.z; ng[7] += h0.w;
                    }
                    if (i + 1 >= m) {
                        ng[0] += l1.x; ng[1] += l1.y; ng[2] += l1.z; ng[3] += l1.w;
                        ng[4] += h1.x; ng[5] += h1.y; ng[6] += h1.z; ng[7] += h1.w;
                    }
                }
            }
        }
        __syncthreads();
    }

    // ---- reductions: per row {gain, loss, ysurf, ymant} (red/tot alias lbuf) ----
    float vals[32];
    #pragma unroll
    for (int v = 0; v < 32; v++) vals[v] = 0.f;
    #pragma unroll
    for (int gsp = 0; gsp < SPT; gsp++) {
        int s = tid + gsp * NT;
        float4 ya = ylo[s], yb = yhi[s];
        float yr[ROWS] = { ya.x, ya.y, ya.z, ya.w, yb.x, yb.y, yb.z, yb.w };
        if (isSurf[gsp]) {
            #pragma unroll
            for (int r = 0; r < ROWS; r++) {
                vals[4 * r + 0] += net[gsp][r] + ng[r];
                vals[4 * r + 1] += ng[r];
                vals[4 * r + 2] += yr[r];
            }
        } else if (isMant[gsp]) {
            #pragma unroll
            for (int r = 0; r < ROWS; r++) vals[4 * r + 3] += yr[r];
        }
    }
    {
        int lane = tid & 31, w = tid >> 5;
        #pragma unroll
        for (int v = 0; v < 32; v++) {
            float x = warp_red(vals[v]);
            if (lane == 0) red[v][w] = x;
        }
        __syncthreads();
        if (tid < 32) {
            float s = 0.f;
            #pragma unroll
            for (int i = 0; i < NT / 32; i++) s += red[tid][i];
            tot[tid] = s;
        }
        __syncthreads();
    }

    float ks2m[ROWS], km2s[ROWS];
    #pragma unroll
    for (int r = 0; r < ROWS; r++) {
        ks2m[r] = tot[4 * r + 0] / (tot[4 * r + 2] + 1e-10f);
        km2s[r] = tot[4 * r + 1] / (tot[4 * r + 3] + 1e-10f);
    }

    // ---- epilogue: surface<->mantle transfer + write out ----
    #pragma unroll
    for (int gsp = 0; gsp < SPT; gsp++) {
        int s = tid + gsp * NT;
        float dy[ROWS];
        #pragma unroll
        for (int r = 0; r < ROWS; r++) dy[r] = net[gsp][r];
        unsigned ds = (unsigned)(s - s0), dm = (unsigned)(s - m0);
        if (ds < NSS) {
            float4 ma = ylo[m0 + ds], mb = yhi[m0 + ds];
            float4 sa = ylo[s],       sb = yhi[s];
            float ymr[ROWS] = { ma.x, ma.y, ma.z, ma.w, mb.x, mb.y, mb.z, mb.w };
            float ysr[ROWS] = { sa.x, sa.y, sa.z, sa.w, sb.x, sb.y, sb.z, sb.w };
            #pragma unroll
            for (int r = 0; r < ROWS; r++) dy[r] += km2s[r] * ymr[r] - ks2m[r] * ysr[r];
        } else if (dm < NSS) {
            float4 sa = ylo[s0 + dm], sb = yhi[s0 + dm];
            float4 ma = ylo[s],       mb = yhi[s];
            float ysr[ROWS] = { sa.x, sa.y, sa.z, sa.w, sb.x, sb.y, sb.z, sb.w };
            float ymr[ROWS] = { ma.x, ma.y, ma.z, ma.w, mb.x, mb.y, mb.z, mb.w };
            #pragma unroll
            for (int r = 0; r < ROWS; r++) dy[r] += ks2m[r] * ysr[r] - km2s[r] * ymr[r];
        }
        #pragma unroll
        for (int r = 0; r < ROWS; r++)
            out[(size_t)(b0 + r) * SB + s] = dy[r];
    }
}

extern "C" void kernel_launch(void* const* d_in, const int* in_sizes, int n_in,
                              void* d_out, int out_size) {
    const float* t_in    = (const float*)d_in[0];
    const float* y_in    = (const float*)d_in[1];
    const float* den_gas = (const float*)d_in[2];
    const float* a1      = (const float*)d_in[3];
    const float* g1      = (const float*)d_in[4];
    const float* a2      = (const float*)d_in[5];
    const float* g2      = (const float*)d_in[6];
    const int*   r11     = (const int*)d_in[7];
    const int*   p1      = (const int*)d_in[8];
    const int*   r12     = (const int*)d_in[9];
    const int*   r22     = (const int*)d_in[10];
    const int*   p2      = (const int*)d_in[11];
    const int*   inds_s  = (const int*)d_in[12];
    const int*   inds_m  = (const int*)d_in[13];
    float*       out     = (float*)d_out;

    const int B = in_sizes[0];

    cudaFuncSetAttribute(three_phase_rhs,
                         cudaFuncAttributeMaxDynamicSharedMemorySize, SMEM_BYTES);

    k_count<<<(NROLES + 255) / 256, 256>>>(p1, r11, p2, r12, r22);
    k_scan <<<1, 1024>>>();
    k_fill <<<(NROLES + 255) / 256, 256>>>(p1, r11, p2, r12, r22);

    three_phase_rhs<<<B / ROWS, NT, SMEM_BYTES>>>(
        t_in, y_in, den_gas, a1, g1, a2, g2,
        r11, r12, r22, inds_s, inds_m, out);
}

// round 17
// speedup vs baseline: 1.5374x; 1.2903x over previous
#include <cuda_runtime.h>
#include <cuda_fp16.h>

// ---- problem constants ----
#define SB      1024
#define N1      8192
#define N2      16384
#define NTERMS  (N1 + N2)            // 24576
#define NC      8                    // chunks
#define CHUNK   3072                 // NC*CHUNK == NTERMS exactly
#define NSS     256
#define NT      512
#define ROWS    8
#define SPT     (SB / NT)            // 2 species per thread
#define NCTR    (NC * SB)            // 8192 sublists, chunk-major: sub = c*SB + s
#define NROLES  (2 * N1 + 3 * N2)    // 65536
#define LIST_CAP 77936               // 65536 + pads + alignment + slack
#define LCAP    10752                // >= worst slice (3*CHUNK + SB + 8 = 10248)

// ---- persistent scratch (rebuilt every launch; structure is input-constant) ----
__device__ int g_cnt[2 * NCTR];      // (sublist, gain/loss) counts — static zero init
__device__ int g_curG[NCTR];
__device__ int g_curL[NCTR];
__device__ int g_off[NCTR + 1];      // padded sublist starts; chunk slices 8-aligned
__device__ int g_mid[NCTR];          // gain/loss boundary
__device__ __align__(16) unsigned short g_list[LIST_CAP];

// dynamic smem: thf uint4[CHUNK+1] (8 fp16 rows/term) | ylo f4[SB] | yhi f4[SB] | lbuf u16[LCAP]
// (reduction scratch red/tot aliases lbuf — lbuf dead by reduction time)
#define SMEM_BYTES ((CHUNK + 1) * 16 + 2 * SB * 16 + LCAP * 2)   // 103,440 B

__inline__ __device__ float warp_red(float v) {
    #pragma unroll
    for (int o = 16; o > 0; o >>= 1) v += __shfl_xor_sync(0xFFFFFFFFu, v, o);
    return v;
}

// ---------- build kernels (3 launches) ----------
__device__ __forceinline__ void decode_role(
    int id, const int* p1, const int* r11, const int* p2,
    const int* r12, const int* r22, int& term, int& s, int& loss)
{
    if (id < N1)                 { term = id;                  s = __ldg(p1  + id);          loss = 0; }
    else if (id < 2 * N1)        { term = id - N1;             s = __ldg(r11 + id - N1);     loss = 1; }
    else if (id < 2 * N1 + N2)   { int j = id - 2 * N1;        term = N1 + j; s = __ldg(p2  + j); loss = 0; }
    else if (id < 2 * N1 + 2*N2) { int j = id - 2 * N1 - N2;   term = N1 + j; s = __ldg(r12 + j); loss = 1; }
    else                         { int j = id - 2 * N1 - 2*N2; term = N1 + j; s = __ldg(r22 + j); loss = 1; }
}

__global__ void k_count(const int* __restrict__ p1, const int* __restrict__ r11,
                        const int* __restrict__ p2, const int* __restrict__ r12,
                        const int* __restrict__ r22) {
    int id = blockIdx.x * blockDim.x + threadIdx.x;
    if (id >= NROLES) return;
    int term, s, loss;
    decode_role(id, p1, r11, p2, r12, r22, term, s, loss);
    int sub = (term / CHUNK) * SB + s;
    atomicAdd(&g_cnt[2 * sub + loss], 1);
}

__global__ void k_scan() {   // 1 CTA, 1024 threads; per-chunk shuffle scan
    __shared__ int wsum[32];
    __shared__ int chunkBase;
    const int t = threadIdx.x, lane = t & 31, w = t >> 5;
    if (t == 0) chunkBase = 0;
    __syncthreads();
    for (int c = 0; c < NC; c++) {
        const int sub = c * SB + t;
        const int gcv = g_cnt[2 * sub];
        const int lcv = g_cnt[2 * sub + 1];
        const int pcv = (gcv + lcv + 1) & ~1;          // pad sublist to 2
        int v = pcv;
        #pragma unroll
        for (int o = 1; o < 32; o <<= 1) {
            int x = __shfl_up_sync(0xFFFFFFFFu, v, o);
            if (lane >= o) v += x;
        }
        if (lane == 31) wsum[w] = v;
        __syncthreads();
        if (w == 0) {
            int wv = wsum[lane];
            #pragma unroll
            for (int o = 1; o < 32; o <<= 1) {
                int x = __shfl_up_sync(0xFFFFFFFFu, wv, o);
                if (lane >= o) wv += x;
            }
            wsum[lane] = wv;
        }
        __syncthreads();
        const int excl = chunkBase + (w ? wsum[w - 1] : 0) + v - pcv;
        g_off[sub]  = excl;
        g_curG[sub] = excl;
        g_mid[sub]  = excl + gcv;
        g_curL[sub] = excl + gcv;
        if ((gcv + lcv) < pcv)                          // odd count -> one dummy slot
            g_list[excl + gcv + lcv] = (unsigned short)CHUNK;
        g_cnt[2 * sub] = 0;                             // re-zero for next launch
        g_cnt[2 * sub + 1] = 0;
        __syncthreads();
        if (t == 1023) {
            int trueEnd = excl + pcv;                   // chunk's true slice end
            int aligned = (trueEnd + 7) & ~7;
            for (int p = trueEnd; p < aligned; p++)     // fill alignment gap
                g_list[p] = (unsigned short)CHUNK;
            chunkBase = aligned;
        }
        __syncthreads();
    }
    if (t == 0) g_off[NCTR] = chunkBase;
}

__global__ void k_fill(const int* __restrict__ p1, const int* __restrict__ r11,
                       const int* __restrict__ p2, const int* __restrict__ r12,
                       const int* __restrict__ r22) {
    int id = blockIdx.x * blockDim.x + threadIdx.x;
    if (id >= NROLES) return;
    int term, s, loss;
    decode_role(id, p1, r11, p2, r12, r22, term, s, loss);
    int c = term / CHUNK;
    int sub = c * SB + s;
    int pos = loss ? atomicAdd(&g_curL[sub], 1) : atomicAdd(&g_curG[sub], 1);
    g_list[pos] = (unsigned short)(term - c * CHUNK);
}

// ---------- main kernel: 8 rows/CTA, NT=512, 2 CTAs/SM, fp16 terms ----------
__global__ __launch_bounds__(NT, 2) void three_phase_rhs(
    const float* __restrict__ t_in, const float* __restrict__ y_in,
    const float* __restrict__ den_gas,
    const float* __restrict__ a1, const float* __restrict__ g1,
    const float* __restrict__ a2, const float* __restrict__ g2,
    const int* __restrict__ r11, const int* __restrict__ r12,
    const int* __restrict__ r22,
    const int* __restrict__ inds_s, const int* __restrict__ inds_m,
    float* __restrict__ out)
{
    extern __shared__ float4 smem4[];
    uint4*  thf = (uint4*)smem4;                  // [CHUNK+1]: 8 fp16 rows per term
    float4* ylo = (float4*)(thf + (CHUNK + 1));   // y rows 0-3
    float4* yhi = ylo + SB;                       // y rows 4-7
    unsigned short* lbuf = (unsigned short*)(yhi + SB);   // [LCAP]
    // reduction scratch aliases lbuf (live only after the chunk loop)
    float (*red)[NT / 32] = (float (*)[NT / 32])lbuf;
    float* tot = (float*)lbuf + 32 * (NT / 32);
    __shared__ float sh_pr[16];                   // nI[0..7] | c2[0..7]

    const int tid = threadIdx.x;
    const int b0 = blockIdx.x * ROWS;

    {
        const float* yr = y_in + (size_t)b0 * SB;
        for (int i = tid; i < SB; i += NT) {
            ylo[i] = make_float4(yr[i], yr[i + SB], yr[i + 2 * SB], yr[i + 3 * SB]);
            yhi[i] = make_float4(yr[i + 4 * SB], yr[i + 5 * SB], yr[i + 6 * SB], yr[i + 7 * SB]);
        }
    }
    if (tid == 0) thf[CHUNK] = make_uint4(0u, 0u, 0u, 0u);   // fp16 zeros
    if (tid < ROWS) {                             // per-row params -> shared
        float T = 10.0f + 5.0f / (1.0f + __expf(-__ldg(t_in + b0 + tid)));
        sh_pr[tid] = -1.0f / T;
        sh_pr[tid + 8] = sqrtf(T * (1.0f / 300.0f)) * __ldg(den_gas + b0 + tid);
    }
    const int s0 = __ldg(&inds_s[0]), m0 = __ldg(&inds_m[0]);

    bool isSurf[SPT], isMant[SPT];
    #pragma unroll
    for (int gsp = 0; gsp < SPT; gsp++) {
        int s = tid + gsp * NT;
        isSurf[gsp] = (unsigned)(s - s0) < NSS;
        isMant[gsp] = (unsigned)(s - m0) < NSS;
    }
    __syncthreads();

    float net[SPT][ROWS];
    float ng[ROWS];
    #pragma unroll
    for (int g = 0; g < SPT; g++)
        #pragma unroll
        for (int r = 0; r < ROWS; r++) net[g][r] = 0.f;
    #pragma unroll
    for (int r = 0; r < ROWS; r++) ng[r] = 0.f;

    for (int c = 0; c < NC; c++) {
        const int base = c * CHUNK;

        // prefetch this chunk's sublist offsets (L2 latency hides under phase 1)
        int beg[SPT], mid[SPT], end[SPT];
        #pragma unroll
        for (int gsp = 0; gsp < SPT; gsp++) {
            const int ob = c * SB + tid + gsp * NT;
            beg[gsp] = __ldg(&g_off[ob]);
            mid[gsp] = __ldg(&g_mid[ob]);
            end[gsp] = __ldg(&g_off[ob + 1]);
        }
        const int sliceBeg = __ldg(&g_off[c * SB]);           // 8-aligned
        const int sliceEnd = __ldg(&g_off[(c + 1) * SB]);     // 8-aligned

        // stage this chunk's list slice into shared (slice <= 10248 <= LCAP always)
        {
            const int n16 = (sliceEnd - sliceBeg) >> 3;
            const uint4* src = (const uint4*)(g_list + sliceBeg);
            uint4* dst = (uint4*)lbuf;
            for (int k = tid; k < n16; k += NT) dst[k] = src[k];
        }
        const unsigned short* lpt = lbuf - sliceBeg;  // index with global position

        // ---- phase 1: terms for this chunk (fp32 compute, fp16 store) ----
        {
            float nI[ROWS], c2[ROWS];
            #pragma unroll
            for (int r = 0; r < ROWS; r++) { nI[r] = sh_pr[r]; c2[r] = sh_pr[r + 8]; }
            for (int jj = tid; jj < CHUNK; jj += NT) {
                int j = base + jj;
                float4 lo, hi;
                if (j < N1) {
                    float a = __ldg(a1 + j), g = __ldg(g1 + j);
                    int   rr = __ldg(r11 + j);
                    float4 ya = ylo[rr], yb = yhi[rr];
                    lo.x = a * __expf(g * nI[0]) * ya.x;
                    lo.y = a * __expf(g * nI[1]) * ya.y;
                    lo.z = a * __expf(g * nI[2]) * ya.z;
                    lo.w = a * __expf(g * nI[3]) * ya.w;
                    hi.x = a * __expf(g * nI[4]) * yb.x;
                    hi.y = a * __expf(g * nI[5]) * yb.y;
                    hi.z = a * __expf(g * nI[6]) * yb.z;
                    hi.w = a * __expf(g * nI[7]) * yb.w;
                } else {
                    int j2 = j - N1;
                    float a = __ldg(a2 + j2), g = __ldg(g2 + j2);
                    int  rA = __ldg(r12 + j2), rB = __ldg(r22 + j2);
                    float4 yaA = ylo[rA], yaB = ylo[rB];
                    float4 ybA = yhi[rA], ybB = yhi[rB];
                    lo.x = a * c2[0] * __expf(g * nI[0]) * yaA.x * yaB.x;
                    lo.y = a * c2[1] * __expf(g * nI[1]) * yaA.y * yaB.y;
                    lo.z = a * c2[2] * __expf(g * nI[2]) * yaA.z * yaB.z;
                    lo.w = a * c2[3] * __expf(g * nI[3]) * yaA.w * yaB.w;
                    hi.x = a * c2[4] * __expf(g * nI[4]) * ybA.x * ybB.x;
                    hi.y = a * c2[5] * __expf(g * nI[5]) * ybA.y * ybB.y;
                    hi.z = a * c2[6] * __expf(g * nI[6]) * ybA.z * ybB.z;
                    hi.w = a * c2[7] * __expf(g * nI[7]) * ybA.w * ybB.w;
                }
                __half2 p0 = __floats2half2_rn(lo.x, lo.y);
                __half2 p1 = __floats2half2_rn(lo.z, lo.w);
                __half2 p2 = __floats2half2_rn(hi.x, hi.y);
                __half2 p3 = __floats2half2_rn(hi.z, hi.w);
                uint4 pv;
                pv.x = *(unsigned*)&p0; pv.y = *(unsigned*)&p1;
                pv.z = *(unsigned*)&p2; pv.w = *(unsigned*)&p3;
                thf[jj] = pv;
            }
        }
        __syncthreads();   // terms + lbuf both ready

        // ---- phase 2: gather (one LDS.128 per entry; fp32 accumulation) ----
        #pragma unroll
        for (int gsp = 0; gsp < SPT; gsp++) {
            const bool surf = isSurf[gsp];
            const int m = mid[gsp], e = end[gsp];
            for (int i = beg[gsp]; i < e; i += 2) {
                const unsigned w = *(const unsigned*)(lpt + i);
                const int e0 = (int)(w & 0xFFFFu), e1 = (int)(w >> 16);
                uint4 q0 = thf[e0];
                uint4 q1 = thf[e1];
                float2 a0 = __half22float2(*(__half2*)&q0.x);
                float2 a1v = __half22float2(*(__half2*)&q0.y);
                float2 a2v = __half22float2(*(__half2*)&q0.z);
                float2 a3 = __half22float2(*(__half2*)&q0.w);
                float2 b0v = __half22float2(*(__half2*)&q1.x);
                float2 b1 = __half22float2(*(__half2*)&q1.y);
                float2 b2 = __half22float2(*(__half2*)&q1.z);
                float2 b3 = __half22float2(*(__half2*)&q1.w);
                const float sg0 = (i     < m) ? 1.f : -1.f;
                const float sg1 = (i + 1 < m) ? 1.f : -1.f;
                net[gsp][0] = fmaf(sg0, a0.x, net[gsp][0]);
                net[gsp][1] = fmaf(sg0, a0.y, net[gsp][1]);
                net[gsp][2] = fmaf(sg0, a1v.x, net[gsp][2]);
                net[gsp][3] = fmaf(sg0, a1v.y, net[gsp][3]);
                net[gsp][4] = fmaf(sg0, a2v.x, net[gsp][4]);
                net[gsp][5] = fmaf(sg0, a2v.y, net[gsp][5]);
                net[gsp][6] = fmaf(sg0, a3.x, net[gsp][6]);
                net[gsp][7] = fmaf(sg0, a3.y, net[gsp][7]);
                net[gsp][0] = fmaf(sg1, b0v.x, net[gsp][0]);
                net[gsp][1] = fmaf(sg1, b0v.y, net[gsp][1]);
                net[gsp][2] = fmaf(sg1, b1.x, net[gsp][2]);
                net[gsp][3] = fmaf(sg1, b1.y, net[gsp][3]);
                net[gsp][4] = fmaf(sg1, b2.x, net[gsp][4]);
                net[gsp][5] = fmaf(sg1, b2.y, net[gsp][5]);
                net[gsp][6] = fmaf(sg1, b3.x, net[gsp][6]);
                net[gsp][7] = fmaf(sg1, b3.y, net[gsp][7]);
                if (surf) {                       // warp-uniform
                    if (i >= m) {
                        ng[0] += a0.x; ng[1] += a0.y; ng[2] += a1v.x; ng[3] += a1v.y;
                        ng[4] += a2v.x; ng[5] += a2v.y; ng[6] += a3.x; ng[7] += a3.y;
                    }
                    if (i + 1 >= m) {
                        ng[0] += b0v.x; ng[1] += b0v.y; ng[2] += b1.x; ng[3] += b1.y;
                        ng[4] += b2.x; ng[5] += b2.y; ng[6] += b3.x; ng[7] += b3.y;
                    }
                }
            }
        }
        __syncthreads();
    }

    // ---- reductions: per row {gain, loss, ysurf, ymant} (red/tot alias lbuf) ----
    float vals[32];
    #pragma unroll
    for (int v = 0; v < 32; v++) vals[v] = 0.f;
    #pragma unroll
    for (int gsp = 0; gsp < SPT; gsp++) {
        int s = tid + gsp * NT;
        float4 ya = ylo[s], yb = yhi[s];
        float yr[ROWS] = { ya.x, ya.y, ya.z, ya.w, yb.x, yb.y, yb.z, yb.w };
        if (isSurf[gsp]) {
            #pragma unroll
            for (int r = 0; r < ROWS; r++) {
                vals[4 * r + 0] += net[gsp][r] + ng[r];
                vals[4 * r + 1] += ng[r];
                vals[4 * r + 2] += yr[r];
            }
        } else if (isMant[gsp]) {
            #pragma unroll
            for (int r = 0; r < ROWS; r++) vals[4 * r + 3] += yr[r];
        }
    }
    {
        int lane = tid & 31, w = tid >> 5;
        #pragma unroll
        for (int v = 0; v < 32; v++) {
            float x = warp_red(vals[v]);
            if (lane == 0) red[v][w] = x;
        }
        __syncthreads();
        if (tid < 32) {
            float s = 0.f;
            #pragma unroll
            for (int i = 0; i < NT / 32; i++) s += red[tid][i];
            tot[tid] = s;
        }
        __syncthreads();
    }

    float ks2m[ROWS], km2s[ROWS];
    #pragma unroll
    for (int r = 0; r < ROWS; r++) {
        ks2m[r] = tot[4 * r + 0] / (tot[4 * r + 2] + 1e-10f);
        km2s[r] = tot[4 * r + 1] / (tot[4 * r + 3] + 1e-10f);
    }

    // ---- epilogue: surface<->mantle transfer + write out ----
    #pragma unroll
    for (int gsp = 0; gsp < SPT; gsp++) {
        int s = tid + gsp * NT;
        float dy[ROWS];
        #pragma unroll
        for (int r = 0; r < ROWS; r++) dy[r] = net[gsp][r];
        unsigned ds = (unsigned)(s - s0), dm = (unsigned)(s - m0);
        if (ds < NSS) {
            float4 ma = ylo[m0 + ds], mb = yhi[m0 + ds];
            float4 sa = ylo[s],       sb = yhi[s];
            float ymr[ROWS] = { ma.x, ma.y, ma.z, ma.w, mb.x, mb.y, mb.z, mb.w };
            float ysr[ROWS] = { sa.x, sa.y, sa.z, sa.w, sb.x, sb.y, sb.z, sb.w };
            #pragma unroll
            for (int r = 0; r < ROWS; r++) dy[r] += km2s[r] * ymr[r] - ks2m[r] * ysr[r];
        } else if (dm < NSS) {
            float4 sa = ylo[s0 + dm], sb = yhi[s0 + dm];
            float4 ma = ylo[s],       mb = yhi[s];
            float ysr[ROWS] = { sa.x, sa.y, sa.z, sa.w, sb.x, sb.y, sb.z, sb.w };
            float ymr[ROWS] = { ma.x, ma.y, ma.z, ma.w, mb.x, mb.y, mb.z, mb.w };
            #pragma unroll
            for (int r = 0; r < ROWS; r++) dy[r] += ks2m[r] * ysr[r] - km2s[r] * ymr[r];
        }
        #pragma unroll
        for (int r = 0; r < ROWS; r++)
            out[(size_t)(b0 + r) * SB + s] = dy[r];
    }
}

extern "C" void kernel_launch(void* const* d_in, const int* in_sizes, int n_in,
                              void* d_out, int out_size) {
    const float* t_in    = (const float*)d_in[0];
    const float* y_in    = (const float*)d_in[1];
    const float* den_gas = (const float*)d_in[2];
    const float* a1      = (const float*)d_in[3];
    const float* g1      = (const float*)d_in[4];
    const float* a2      = (const float*)d_in[5];
    const float* g2      = (const float*)d_in[6];
    const int*   r11     = (const int*)d_in[7];
    const int*   p1      = (const int*)d_in[8];
    const int*   r12     = (const int*)d_in[9];
    const int*   r22     = (const int*)d_in[10];
    const int*   p2      = (const int*)d_in[11];
    const int*   inds_s  = (const int*)d_in[12];
    const int*   inds_m  = (const int*)d_in[13];
    float*       out     = (float*)d_out;

    const int B = in_sizes[0];

    cudaFuncSetAttribute(three_phase_rhs,
                         cudaFuncAttributeMaxDynamicSharedMemorySize, SMEM_BYTES);

    k_count<<<(NROLES + 255) / 256, 256>>>(p1, r11, p2, r12, r22);
    k_scan <<<1, 1024>>>();
    k_fill <<<(NROLES + 255) / 256, 256>>>(p1, r11, p2, r12, r22);

    three_phase_rhs<<<B / ROWS, NT, SMEM_BYTES>>>(
        t_in, y_in, den_gas, a1, g1, a2, g2,
        r11, r12, r22, inds_s, inds_m, out);
}